// round 15
// baseline (speedup 1.0000x reference)
#include <cuda_runtime.h>
#include <cuda_fp16.h>
#include <cstdint>
#include <cmath>

#define N_NODES 12500
#define N_EDGES 200000
#define OUT_ELEMS (N_NODES * 64)
#define N_PAIRS (N_EDGES / 32)        // 6250 pairs of 16-edge tiles, exact
#define THREADS 640
#define WPB 20

// B pack: main 4blk*16u*32lane*4words + bias 4blk*32lane*4words (uint32 words)
#define BPM_WORDS 8192
#define BPB_WORDS 512
#define BP_WORDS (BPM_WORDS + BPB_WORDS)   // 8704

// per-tile coeff region (uint32 words): cf16[set 0..5][u-pair 0..7][edge 0..15]
#define CS_TILE 768
#define SM_CS  BP_WORDS
#define SM_WORDS (SM_CS + WPB * 2 * CS_TILE)   // 39424
#define SM_BYTES (SM_WORDS * 4)                // 157696

__device__ int      g_src[N_EDGES];
__device__ int      g_dst[N_EDGES];
__device__ float    g_counts[N_NODES];          // raw in-degree counts
__device__ float2   g_ds[N_EDGES];              // (dst bits, alpha/max(cnt,1))
__device__ uint32_t g_h2[(size_t)N_EDGES * 8];  // fp16 h rows (8 half2 words)
__device__ uint32_t g_Bpack[BP_WORDS];          // fragment-order fp16 B + bias-B
__device__ int      g_is64;

// m16n8k16 fp16 HMMA, accumulate in place
__device__ __forceinline__ void mma16(float& e0, float& e1, float& e2, float& e3,
                                      const uint32_t* a, uint32_t b0, uint32_t b1) {
    asm volatile("mma.sync.aligned.m16n8k16.row.col.f32.f16.f16.f32 "
        "{%0,%1,%2,%3}, {%4,%5,%6,%7}, {%8,%9}, {%0,%1,%2,%3};"
        : "+f"(e0), "+f"(e1), "+f"(e2), "+f"(e3)
        : "r"(a[0]), "r"(a[1]), "r"(a[2]), "r"(a[3]), "r"(b0), "r"(b1));
}

#define RED_V2(p, x, y) \
    asm volatile("red.global.add.v2.f32 [%0], {%1, %2};" \
        :: "l"(p), "f"(x), "f"(y) : "memory")

__device__ __forceinline__ uint32_t h2pack(float a, float b) {
    __half2 h = __floats2half2_rn(a, b);
    return *(uint32_t*)&h;
}
__device__ __forceinline__ float2 h2f2(uint32_t w) {
    return __half22float2(*(__half2*)&w);
}

// k1: detect dtype, zero out/counts, build fp16 fragment-packed B (+bias-B)
__global__ void zero_kernel(const unsigned* __restrict__ ei, float* __restrict__ out,
                            const float* __restrict__ w2, const float* __restrict__ b2) {
    int i = blockIdx.x * blockDim.x + threadIdx.x;
    if (i == 0) {
        int ok = 1;
        for (int j = 0; j < 128; j++) ok &= (ei[2 * j + 1] == 0u);
        g_is64 = ok;
    }
    if (i < OUT_ELEMS) out[i] = 0.f;
    if (i < N_NODES) g_counts[i] = 0.f;
    if (i < BPM_WORDS) {
        int r = i & 3, lane = (i >> 2) & 31, bu = i >> 7;
        int col = (bu >> 4) * 256 + (bu & 15) * 16 + (lane >> 2) + ((r & 2) ? 8 : 0);
        int k0 = 2 * (lane & 3) + ((r & 1) ? 8 : 0);
        g_Bpack[i] = h2pack(w2[k0 * 1024 + col], w2[(k0 + 1) * 1024 + col]);
    } else if (i < BP_WORDS) {
        int j = i - BPM_WORDS;
        int r = j & 3, lane = (j >> 2) & 31, blk = j >> 7;
        int colw = (lane >> 2) + ((r & 2) ? 8 : 0);
        int k0 = 2 * (lane & 3) + ((r & 1) ? 8 : 0);
        g_Bpack[i] = h2pack(b2[blk * 256 + k0 * 16 + colw],
                            b2[blk * 256 + (k0 + 1) * 16 + colw]);
    }
}

// k2: edge_index -> int32, count dsts
__global__ void prep_kernel(const int* __restrict__ ei) {
    int i = blockIdx.x * blockDim.x + threadIdx.x;
    if (i < N_EDGES) {
        int s, d;
        if (g_is64) { s = ei[2 * i]; d = ei[2 * (N_EDGES + i)]; }
        else        { s = ei[i];     d = ei[N_EDGES + i]; }
        g_src[i] = s; g_dst[i] = d;
        atomicAdd(&g_counts[d], 1.f);
    }
}

// k3: h rows = fp16(silu(ea@w1+b1)); also builds g_ds (dst + alpha/count)
__global__ void h_kernel(const float* __restrict__ ea,
                         const float* __restrict__ w1g,
                         const float* __restrict__ b1g) {
    __shared__ float swt[16 * 20], sb[16];     // w1 transposed [k][j], pad 20
    if (threadIdx.x < 256)
        swt[(threadIdx.x & 15) * 20 + (threadIdx.x >> 4)] = w1g[threadIdx.x];
    if (threadIdx.x < 16)  sb[threadIdx.x] = b1g[threadIdx.x];
    __syncthreads();
    int e = blockIdx.x * blockDim.x + threadIdx.x;
    if (e >= N_EDGES) return;
    {
        int d = g_dst[e];
        g_ds[e] = make_float2(__int_as_float(d),
                              0.17677669529663688f / fmaxf(g_counts[d], 1.f));
    }
    const float4* r = (const float4*)(ea + (size_t)e * 16);
    float4 v0 = r[0], v1 = r[1], v2 = r[2], v3 = r[3];
    float o[16];
    #pragma unroll
    for (int k = 0; k < 16; k++) {
        const float4* wr = (const float4*)(swt + k * 20);
        float4 w0 = wr[0], w1v = wr[1], w2v = wr[2], w3v = wr[3];
        float t = sb[k];
        t = fmaf(v0.x, w0.x, t); t = fmaf(v0.y, w0.y, t);
        t = fmaf(v0.z, w0.z, t); t = fmaf(v0.w, w0.w, t);
        t = fmaf(v1.x, w1v.x, t); t = fmaf(v1.y, w1v.y, t);
        t = fmaf(v1.z, w1v.z, t); t = fmaf(v1.w, w1v.w, t);
        t = fmaf(v2.x, w2v.x, t); t = fmaf(v2.y, w2v.y, t);
        t = fmaf(v2.z, w2v.z, t); t = fmaf(v2.w, w2v.w, t);
        t = fmaf(v3.x, w3v.x, t); t = fmaf(v3.y, w3v.y, t);
        t = fmaf(v3.z, w3v.z, t); t = fmaf(v3.w, w3v.w, t);
        o[k] = t / (1.f + __expf(-t));
    }
    uint32_t w[8];
    #pragma unroll
    for (int m = 0; m < 8; m++) w[m] = h2pack(o[2 * m], o[2 * m + 1]);
    uint4* dst = (uint4*)(g_h2 + (size_t)e * 8);
    dst[0] = make_uint4(w[0], w[1], w[2], w[3]);
    dst[1] = make_uint4(w[4], w[5], w[6], w[7]);
}

// ---------------------------------------------------------------------------
// k4: conv. One warp = 32 edges (2 tiles). cf16 layout [set][u-pair][edge].
// WARP-MAJOR pair mapping: gw = warp*gridDim + block, so the 170 leftover
// passes spread one-per-SM instead of piling onto blocks 0-8.
// ---------------------------------------------------------------------------
__global__ void __launch_bounds__(THREADS, 1) conv_kernel(
    const float*  __restrict__ node_attr,
    const float4* __restrict__ edge_sh4,
    float*        __restrict__ out)
{
    extern __shared__ float sm[];
    const int tid = threadIdx.x, lane = tid & 31, warp = tid >> 5;
    const int g = lane >> 2, tig = lane & 3;

    for (int i = tid; i < BP_WORDS / 4; i += THREADS)
        ((uint4*)sm)[i] = ((const uint4*)g_Bpack)[i];
    __syncthreads();

    uint32_t* cs0 = (uint32_t*)sm + SM_CS + warp * 2 * CS_TILE;
    uint32_t* cs1 = cs0 + CS_TILE;
    const int eL = lane & 15, u0 = (lane >> 4) * 8, mp0 = u0 >> 1;
    const float inv3 = 0.57735026918962576f;      // 1/sqrt(3)

    const float4* Bp  = (const float4*)sm + lane;          // + (blk*16+u)*32
    const float4* BpB = (const float4*)sm + 2048 + lane;   // + blk*32

    // warp-major mapping: leftover passes distribute across all SMs
    const int gwarp = warp * gridDim.x + blockIdx.x;

    for (int p = gwarp; p < N_PAIRS; p += gridDim.x * WPB) {
        const int e0 = p * 32;

        // ---- coefficient staging (u-pair packed fp16) ----
        __syncwarp();
        #pragma unroll
        for (int tt = 0; tt < 2; tt++) {
            uint32_t* ct = tt ? cs1 : cs0;
            int eg = e0 + tt * 16 + eL;
            int sn = g_src[eg];
            float4 sh = edge_sh4[eg];
            const float* na = node_attr + (size_t)sn * 64;
            float4 x0a = ((const float4*)(na + u0))[0];
            float4 x0b = ((const float4*)(na + u0))[1];
            float x0v[8] = {x0a.x, x0a.y, x0a.z, x0a.w, x0b.x, x0b.y, x0b.z, x0b.w};
            union { float4 v[6]; float f[24]; } x1;
            const float4* xp = (const float4*)(na + 16 + 3 * u0);
            #pragma unroll
            for (int m = 0; m < 6; m++) x1.v[m] = xp[m];
            #pragma unroll
            for (int m = 0; m < 4; m++) {
                float cA[6], cB[6];
                #pragma unroll
                for (int q = 0; q < 2; q++) {
                    int i = 2 * m + q;
                    float* c = q ? cB : cA;
                    float x0 = x0v[i];
                    float xa = x1.f[3*i], xb = x1.f[3*i+1], xc = x1.f[3*i+2];
                    c[0] = x0 * sh.x;
                    c[1] = inv3 * (xa*sh.y + xb*sh.z + xc*sh.w);
                    c[2] = x0;
                    c[3] = sh.x * xa; c[4] = sh.x * xb; c[5] = sh.x * xc;
                }
                #pragma unroll
                for (int s = 0; s < 6; s++)
                    ct[s * 128 + (mp0 + m) * 16 + eL] = h2pack(cA[s], cB[s]);
            }
        }
        __syncwarp();

        // ---- A fragments, both tiles ----
        uint32_t a0[4], a1[4];
        a0[0] = g_h2[(size_t)(e0 + g)      * 8 + tig];
        a0[1] = g_h2[(size_t)(e0 + g + 8)  * 8 + tig];
        a0[2] = g_h2[(size_t)(e0 + g)      * 8 + tig + 4];
        a0[3] = g_h2[(size_t)(e0 + g + 8)  * 8 + tig + 4];
        a1[0] = g_h2[(size_t)(e0 + 16 + g)     * 8 + tig];
        a1[1] = g_h2[(size_t)(e0 + 16 + g + 8) * 8 + tig];
        a1[2] = g_h2[(size_t)(e0 + 16 + g)     * 8 + tig + 4];
        a1[3] = g_h2[(size_t)(e0 + 16 + g + 8) * 8 + tig + 4];

        // bias A-fragment: direct loads (u-pair layout == fragment layout)
#define BIAS_A(CT, S, ba) \
        uint32_t ba[4]; \
        ba[0] = (CT)[(S)*128 + tig*16 + g];     ba[1] = (CT)[(S)*128 + tig*16 + g + 8]; \
        ba[2] = (CT)[(S)*128 + (tig+4)*16 + g]; ba[3] = (CT)[(S)*128 + (tig+4)*16 + g + 8];

#define BIAS_MMA(A, ba, BLK) { \
        float4 bb = BpB[(BLK) * 32]; \
        mma16(A[0], A[1], A[4], A[5], ba, __float_as_uint(bb.x), __float_as_uint(bb.y)); \
        mma16(A[2], A[3], A[6], A[7], ba, __float_as_uint(bb.z), __float_as_uint(bb.w)); }

#define MMA4(BLK, U) \
        float d00[4] = {0.f,0.f,0.f,0.f}, d01[4] = {0.f,0.f,0.f,0.f}; \
        float d10[4] = {0.f,0.f,0.f,0.f}, d11[4] = {0.f,0.f,0.f,0.f}; \
        { float4 bv = Bp[((BLK)*16 + (U)) * 32]; \
          uint32_t b0 = __float_as_uint(bv.x), b1 = __float_as_uint(bv.y); \
          uint32_t b2w = __float_as_uint(bv.z), b3 = __float_as_uint(bv.w); \
          mma16(d00[0], d00[1], d00[2], d00[3], a0, b0, b1); \
          mma16(d01[0], d01[1], d01[2], d01[3], a0, b2w, b3); \
          mma16(d10[0], d10[1], d10[2], d10[3], a1, b0, b1); \
          mma16(d11[0], d11[1], d11[2], d11[3], a1, b2w, b3); }

#define ACC8S(A, CX, CY, D0, D1) { \
        A[0] += (CX)*D0[0]; A[1] += (CX)*D0[1]; A[4] += (CY)*D0[2]; A[5] += (CY)*D0[3]; \
        A[2] += (CX)*D1[0]; A[3] += (CX)*D1[1]; A[6] += (CY)*D1[2]; A[7] += (CY)*D1[3]; }

        // ---- phase 1: out0 (blocks 0,1) both tiles, then flush ----
        {
            float A0[8] = {}, A1[8] = {};
            { BIAS_A(cs0, 0, b00) BIAS_MMA(A0, b00, 0) }
            { BIAS_A(cs0, 1, b01) BIAS_MMA(A0, b01, 1) }
            { BIAS_A(cs1, 0, b10) BIAS_MMA(A1, b10, 0) }
            { BIAS_A(cs1, 1, b11) BIAS_MMA(A1, b11, 1) }
            #pragma unroll 2
            for (int m = 0; m < 8; m++) {
                float2 c0g0 = h2f2(cs0[0*128 + m*16 + g]), c0h0 = h2f2(cs0[0*128 + m*16 + g+8]);
                float2 c1g0 = h2f2(cs0[1*128 + m*16 + g]), c1h0 = h2f2(cs0[1*128 + m*16 + g+8]);
                float2 c0g1 = h2f2(cs1[0*128 + m*16 + g]), c0h1 = h2f2(cs1[0*128 + m*16 + g+8]);
                float2 c1g1 = h2f2(cs1[1*128 + m*16 + g]), c1h1 = h2f2(cs1[1*128 + m*16 + g+8]);
                #pragma unroll
                for (int q = 0; q < 2; q++) {
                    int u = 2*m + q;
                    { MMA4(0, u)
                      ACC8S(A0, (q?c0g0.y:c0g0.x), (q?c0h0.y:c0h0.x), d00, d01)
                      ACC8S(A1, (q?c0g1.y:c0g1.x), (q?c0h1.y:c0h1.x), d10, d11) }
                    { MMA4(1, u)
                      ACC8S(A0, (q?c1g0.y:c1g0.x), (q?c1h0.y:c1h0.x), d00, d01)
                      ACC8S(A1, (q?c1g1.y:c1g1.x), (q?c1h1.y:c1h1.x), d10, d11) }
                }
            }
            #pragma unroll
            for (int tt = 0; tt < 2; tt++) {
                float* A = tt ? A1 : A0;
                float2 dsg = g_ds[e0 + tt*16 + g];
                float2 dsh = g_ds[e0 + tt*16 + g + 8];
                float* og = out + (size_t)__float_as_int(dsg.x) * 64;
                float* oh = out + (size_t)__float_as_int(dsh.x) * 64;
                RED_V2(og + 2*tig,     dsg.y * A[0], dsg.y * A[1]);
                RED_V2(og + 8 + 2*tig, dsg.y * A[2], dsg.y * A[3]);
                RED_V2(oh + 2*tig,     dsh.y * A[4], dsh.y * A[5]);
                RED_V2(oh + 8 + 2*tig, dsh.y * A[6], dsh.y * A[7]);
            }
        }

        // ---- phase 2: tA (block 2) both tiles ----
        float T0[8] = {}, T1[8] = {};
        { BIAS_A(cs0, 2, b20) BIAS_MMA(T0, b20, 2) }
        { BIAS_A(cs1, 2, b21) BIAS_MMA(T1, b21, 2) }
        #pragma unroll 2
        for (int m = 0; m < 8; m++) {
            float2 cg0 = h2f2(cs0[2*128 + m*16 + g]), ch0 = h2f2(cs0[2*128 + m*16 + g+8]);
            float2 cg1 = h2f2(cs1[2*128 + m*16 + g]), ch1 = h2f2(cs1[2*128 + m*16 + g+8]);
            #pragma unroll
            for (int q = 0; q < 2; q++) {
                int u = 2*m + q;
                MMA4(2, u)
                ACC8S(T0, (q?cg0.y:cg0.x), (q?ch0.y:ch0.x), d00, d01)
                ACC8S(T1, (q?cg1.y:cg1.x), (q?ch1.y:ch1.x), d10, d11)
            }
        }

        // ---- phase 3: blk3 per tile (oA/oB/oC), fused out1 flush ----
        #pragma unroll
        for (int tt = 0; tt < 2; tt++) {
            uint32_t* ct = tt ? cs1 : cs0;
            const uint32_t* at = tt ? a1 : a0;
            float* T = tt ? T1 : T0;
            float P[8] = {}, Q[8] = {}, R[8] = {};
            { BIAS_A(ct, 3, b3) BIAS_MMA(P, b3, 3) }
            { BIAS_A(ct, 4, b4) BIAS_MMA(Q, b4, 3) }
            { BIAS_A(ct, 5, b5) BIAS_MMA(R, b5, 3) }
            #pragma unroll 2
            for (int m = 0; m < 8; m++) {
                float2 pg = h2f2(ct[3*128 + m*16 + g]), ph = h2f2(ct[3*128 + m*16 + g+8]);
                float2 qg = h2f2(ct[4*128 + m*16 + g]), qh = h2f2(ct[4*128 + m*16 + g+8]);
                float2 rg = h2f2(ct[5*128 + m*16 + g]), rh = h2f2(ct[5*128 + m*16 + g+8]);
                #pragma unroll
                for (int q2 = 0; q2 < 2; q2++) {
                    int u = 2*m + q2;
                    float dd0[4] = {0.f,0.f,0.f,0.f}, dd1[4] = {0.f,0.f,0.f,0.f};
                    { float4 bv = Bp[(3*16 + u) * 32];
                      mma16(dd0[0], dd0[1], dd0[2], dd0[3], at,
                            __float_as_uint(bv.x), __float_as_uint(bv.y));
                      mma16(dd1[0], dd1[1], dd1[2], dd1[3], at,
                            __float_as_uint(bv.z), __float_as_uint(bv.w)); }
                    ACC8S(P, (q2?pg.y:pg.x), (q2?ph.y:ph.x), dd0, dd1)
                    ACC8S(Q, (q2?qg.y:qg.x), (q2?qh.y:qh.x), dd0, dd1)
                    ACC8S(R, (q2?rg.y:rg.x), (q2?rh.y:rh.x), dd0, dd1)
                }
            }
            // flush out1 for this tile
            #pragma unroll
            for (int r2 = 0; r2 < 2; r2++) {
                int eg = e0 + tt*16 + g + r2*8;
                float4 sh = edge_sh4[eg];
                float2 ds = g_ds[eg];
                float sca = ds.y;
                float* o = out + (size_t)__float_as_int(ds.x) * 64;
                #pragma unroll
                for (int wh = 0; wh < 2; wh++) {
                    int i0 = r2*4 + wh*2, i1 = i0 + 1;
                    float* ob = o + 16 + 24*wh + 6*tig;
                    float t0 = T[i0], t1 = T[i1];
                    RED_V2(ob,     sca * (sh.y*t0 + P[i0]), sca * (sh.z*t0 + Q[i0]));
                    RED_V2(ob + 2, sca * (sh.w*t0 + R[i0]), sca * (sh.y*t1 + P[i1]));
                    RED_V2(ob + 4, sca * (sh.z*t1 + Q[i1]), sca * (sh.w*t1 + R[i1]));
                }
            }
        }
#undef BIAS_A
#undef BIAS_MMA
#undef MMA4
#undef ACC8S
    }
}

extern "C" void kernel_launch(void* const* d_in, const int* in_sizes, int n_in,
                              void* d_out, int out_size) {
    const float* node_attr  = (const float*)d_in[0];
    const void*  edge_index = d_in[1];
    const float* edge_attr  = (const float*)d_in[2];
    const float* edge_sh    = (const float*)d_in[3];
    const float* w1 = (const float*)d_in[4];
    const float* b1 = (const float*)d_in[5];
    const float* w2 = (const float*)d_in[6];
    const float* b2 = (const float*)d_in[7];
    float* out = (float*)d_out;

    cudaFuncSetAttribute(conv_kernel, cudaFuncAttributeMaxDynamicSharedMemorySize, SM_BYTES);

    int smCount = 148;
    cudaDeviceGetAttribute(&smCount, cudaDevAttrMultiProcessorCount, 0);

    zero_kernel<<<(OUT_ELEMS + 255) / 256, 256>>>((const unsigned*)edge_index, out, w2, b2);
    prep_kernel<<<(N_EDGES + 255) / 256, 256>>>((const int*)edge_index);
    h_kernel<<<(N_EDGES + 255) / 256, 256>>>(edge_attr, w1, b1);
    conv_kernel<<<smCount, THREADS, SM_BYTES>>>(node_attr, (const float4*)edge_sh, out);
}

// round 16
// speedup vs baseline: 1.5164x; 1.5164x over previous
#include <cuda_runtime.h>
#include <cuda_fp16.h>
#include <cstdint>
#include <cmath>

#define N_NODES 12500
#define N_EDGES 200000
#define OUT_ELEMS (N_NODES * 64)
#define N_PAIRS (N_EDGES / 32)        // 6250 pairs of 16-edge tiles, exact
#define THREADS 640
#define WPB 20

// B pack: main 4blk*16u*32lane*4words + bias 4blk*32lane*4words (uint32 words)
#define BPM_WORDS 8192
#define BPB_WORDS 512
#define BP_WORDS (BPM_WORDS + BPB_WORDS)   // 8704

// per-tile coeff region (uint32 words): cf16[set 0..5][u-pair 0..7][edge 0..15]
#define CS_TILE 768
#define SM_CS  BP_WORDS
#define SM_WORDS (SM_CS + WPB * 2 * CS_TILE)   // 39424
#define SM_BYTES (SM_WORDS * 4)                // 157696

__device__ int      g_src[N_EDGES];
__device__ int      g_dst[N_EDGES];
__device__ float    g_counts[N_NODES];          // raw in-degree counts
__device__ float2   g_ds[N_EDGES];              // (dst bits, alpha/max(cnt,1))
__device__ uint32_t g_h2[(size_t)N_EDGES * 8];  // fp16 h rows (8 half2 words)
__device__ uint32_t g_Bpack[BP_WORDS];          // fragment-order fp16 B + bias-B
__device__ int      g_is64;

// m16n8k16 fp16 HMMA, accumulate in place
__device__ __forceinline__ void mma16(float& e0, float& e1, float& e2, float& e3,
                                      const uint32_t* a, uint32_t b0, uint32_t b1) {
    asm volatile("mma.sync.aligned.m16n8k16.row.col.f32.f16.f16.f32 "
        "{%0,%1,%2,%3}, {%4,%5,%6,%7}, {%8,%9}, {%0,%1,%2,%3};"
        : "+f"(e0), "+f"(e1), "+f"(e2), "+f"(e3)
        : "r"(a[0]), "r"(a[1]), "r"(a[2]), "r"(a[3]), "r"(b0), "r"(b1));
}

#define RED_V2(p, x, y) \
    asm volatile("red.global.add.v2.f32 [%0], {%1, %2};" \
        :: "l"(p), "f"(x), "f"(y) : "memory")

__device__ __forceinline__ uint32_t h2pack(float a, float b) {
    __half2 h = __floats2half2_rn(a, b);
    return *(uint32_t*)&h;
}
__device__ __forceinline__ float2 h2f2(uint32_t w) {
    return __half22float2(*(__half2*)&w);
}

// k1: detect dtype, zero out/counts, build fp16 fragment-packed B (+bias-B)
__global__ void zero_kernel(const unsigned* __restrict__ ei, float* __restrict__ out,
                            const float* __restrict__ w2, const float* __restrict__ b2) {
    int i = blockIdx.x * blockDim.x + threadIdx.x;
    if (i == 0) {
        int ok = 1;
        for (int j = 0; j < 128; j++) ok &= (ei[2 * j + 1] == 0u);
        g_is64 = ok;
    }
    if (i < OUT_ELEMS) out[i] = 0.f;
    if (i < N_NODES) g_counts[i] = 0.f;
    if (i < BPM_WORDS) {
        int r = i & 3, lane = (i >> 2) & 31, bu = i >> 7;
        int col = (bu >> 4) * 256 + (bu & 15) * 16 + (lane >> 2) + ((r & 2) ? 8 : 0);
        int k0 = 2 * (lane & 3) + ((r & 1) ? 8 : 0);
        g_Bpack[i] = h2pack(w2[k0 * 1024 + col], w2[(k0 + 1) * 1024 + col]);
    } else if (i < BP_WORDS) {
        int j = i - BPM_WORDS;
        int r = j & 3, lane = (j >> 2) & 31, blk = j >> 7;
        int colw = (lane >> 2) + ((r & 2) ? 8 : 0);
        int k0 = 2 * (lane & 3) + ((r & 1) ? 8 : 0);
        g_Bpack[i] = h2pack(b2[blk * 256 + k0 * 16 + colw],
                            b2[blk * 256 + (k0 + 1) * 16 + colw]);
    }
}

// k2: edge_index -> int32, count dsts
__global__ void prep_kernel(const int* __restrict__ ei) {
    int i = blockIdx.x * blockDim.x + threadIdx.x;
    if (i < N_EDGES) {
        int s, d;
        if (g_is64) { s = ei[2 * i]; d = ei[2 * (N_EDGES + i)]; }
        else        { s = ei[i];     d = ei[N_EDGES + i]; }
        g_src[i] = s; g_dst[i] = d;
        atomicAdd(&g_counts[d], 1.f);
    }
}

// k3: h rows = fp16(silu(ea@w1+b1)); also builds g_ds (dst + alpha/count)
__global__ void h_kernel(const float* __restrict__ ea,
                         const float* __restrict__ w1g,
                         const float* __restrict__ b1g) {
    __shared__ float swt[16 * 20], sb[16];     // w1 transposed [k][j], pad 20
    if (threadIdx.x < 256)
        swt[(threadIdx.x & 15) * 20 + (threadIdx.x >> 4)] = w1g[threadIdx.x];
    if (threadIdx.x < 16)  sb[threadIdx.x] = b1g[threadIdx.x];
    __syncthreads();
    int e = blockIdx.x * blockDim.x + threadIdx.x;
    if (e >= N_EDGES) return;
    {
        int d = g_dst[e];
        g_ds[e] = make_float2(__int_as_float(d),
                              0.17677669529663688f / fmaxf(g_counts[d], 1.f));
    }
    const float4* r = (const float4*)(ea + (size_t)e * 16);
    float4 v0 = r[0], v1 = r[1], v2 = r[2], v3 = r[3];
    float o[16];
    #pragma unroll
    for (int k = 0; k < 16; k++) {
        const float4* wr = (const float4*)(swt + k * 20);
        float4 w0 = wr[0], w1v = wr[1], w2v = wr[2], w3v = wr[3];
        float t = sb[k];
        t = fmaf(v0.x, w0.x, t); t = fmaf(v0.y, w0.y, t);
        t = fmaf(v0.z, w0.z, t); t = fmaf(v0.w, w0.w, t);
        t = fmaf(v1.x, w1v.x, t); t = fmaf(v1.y, w1v.y, t);
        t = fmaf(v1.z, w1v.z, t); t = fmaf(v1.w, w1v.w, t);
        t = fmaf(v2.x, w2v.x, t); t = fmaf(v2.y, w2v.y, t);
        t = fmaf(v2.z, w2v.z, t); t = fmaf(v2.w, w2v.w, t);
        t = fmaf(v3.x, w3v.x, t); t = fmaf(v3.y, w3v.y, t);
        t = fmaf(v3.z, w3v.z, t); t = fmaf(v3.w, w3v.w, t);
        o[k] = t / (1.f + __expf(-t));
    }
    uint32_t w[8];
    #pragma unroll
    for (int m = 0; m < 8; m++) w[m] = h2pack(o[2 * m], o[2 * m + 1]);
    uint4* dst = (uint4*)(g_h2 + (size_t)e * 8);
    dst[0] = make_uint4(w[0], w[1], w[2], w[3]);
    dst[1] = make_uint4(w[4], w[5], w[6], w[7]);
}

// ---------------------------------------------------------------------------
// k4: conv. One warp = 32 edges (2 tiles). cf16 layout [set][u-pair][edge].
// Balanced contiguous chunks: block b owns pairs [S, S+nb) with
// nb = 41 + (b<18), S = 41*b + min(b,18); warps round-robin inside the chunk
// (preserves R14's intra-block edge contiguity, removes the 60-vs-40 skew).
// ---------------------------------------------------------------------------
__global__ void __launch_bounds__(THREADS, 1) conv_kernel(
    const float*  __restrict__ node_attr,
    const float4* __restrict__ edge_sh4,
    float*        __restrict__ out)
{
    extern __shared__ float sm[];
    const int tid = threadIdx.x, lane = tid & 31, warp = tid >> 5;
    const int g = lane >> 2, tig = lane & 3;

    for (int i = tid; i < BP_WORDS / 4; i += THREADS)
        ((uint4*)sm)[i] = ((const uint4*)g_Bpack)[i];
    __syncthreads();

    uint32_t* cs0 = (uint32_t*)sm + SM_CS + warp * 2 * CS_TILE;
    uint32_t* cs1 = cs0 + CS_TILE;
    const int eL = lane & 15, u0 = (lane >> 4) * 8, mp0 = u0 >> 1;
    const float inv3 = 0.57735026918962576f;      // 1/sqrt(3)

    const float4* Bp  = (const float4*)sm + lane;          // + (blk*16+u)*32
    const float4* BpB = (const float4*)sm + 2048 + lane;   // + blk*32

    // balanced contiguous chunk for this block
    const int bId = blockIdx.x;
    const int nb = 41 + (bId < 18 ? 1 : 0);
    const int S  = 41 * bId + (bId < 18 ? bId : 18);
    const int pEnd = S + nb;

    for (int p = S + warp; p < pEnd; p += WPB) {
        const int e0 = p * 32;

        // ---- coefficient staging (u-pair packed fp16) ----
        __syncwarp();
        #pragma unroll
        for (int tt = 0; tt < 2; tt++) {
            uint32_t* ct = tt ? cs1 : cs0;
            int eg = e0 + tt * 16 + eL;
            int sn = g_src[eg];
            float4 sh = edge_sh4[eg];
            const float* na = node_attr + (size_t)sn * 64;
            float4 x0a = ((const float4*)(na + u0))[0];
            float4 x0b = ((const float4*)(na + u0))[1];
            float x0v[8] = {x0a.x, x0a.y, x0a.z, x0a.w, x0b.x, x0b.y, x0b.z, x0b.w};
            union { float4 v[6]; float f[24]; } x1;
            const float4* xp = (const float4*)(na + 16 + 3 * u0);
            #pragma unroll
            for (int m = 0; m < 6; m++) x1.v[m] = xp[m];
            #pragma unroll
            for (int m = 0; m < 4; m++) {
                float cA[6], cB[6];
                #pragma unroll
                for (int q = 0; q < 2; q++) {
                    int i = 2 * m + q;
                    float* c = q ? cB : cA;
                    float x0 = x0v[i];
                    float xa = x1.f[3*i], xb = x1.f[3*i+1], xc = x1.f[3*i+2];
                    c[0] = x0 * sh.x;
                    c[1] = inv3 * (xa*sh.y + xb*sh.z + xc*sh.w);
                    c[2] = x0;
                    c[3] = sh.x * xa; c[4] = sh.x * xb; c[5] = sh.x * xc;
                }
                #pragma unroll
                for (int s = 0; s < 6; s++)
                    ct[s * 128 + (mp0 + m) * 16 + eL] = h2pack(cA[s], cB[s]);
            }
        }
        __syncwarp();

        // ---- A fragments, both tiles ----
        uint32_t a0[4], a1[4];
        a0[0] = g_h2[(size_t)(e0 + g)      * 8 + tig];
        a0[1] = g_h2[(size_t)(e0 + g + 8)  * 8 + tig];
        a0[2] = g_h2[(size_t)(e0 + g)      * 8 + tig + 4];
        a0[3] = g_h2[(size_t)(e0 + g + 8)  * 8 + tig + 4];
        a1[0] = g_h2[(size_t)(e0 + 16 + g)     * 8 + tig];
        a1[1] = g_h2[(size_t)(e0 + 16 + g + 8) * 8 + tig];
        a1[2] = g_h2[(size_t)(e0 + 16 + g)     * 8 + tig + 4];
        a1[3] = g_h2[(size_t)(e0 + 16 + g + 8) * 8 + tig + 4];

        // bias A-fragment: direct loads (u-pair layout == fragment layout)
#define BIAS_A(CT, S_, ba) \
        uint32_t ba[4]; \
        ba[0] = (CT)[(S_)*128 + tig*16 + g];     ba[1] = (CT)[(S_)*128 + tig*16 + g + 8]; \
        ba[2] = (CT)[(S_)*128 + (tig+4)*16 + g]; ba[3] = (CT)[(S_)*128 + (tig+4)*16 + g + 8];

#define BIAS_MMA(A, ba, BLK) { \
        float4 bb = BpB[(BLK) * 32]; \
        mma16(A[0], A[1], A[4], A[5], ba, __float_as_uint(bb.x), __float_as_uint(bb.y)); \
        mma16(A[2], A[3], A[6], A[7], ba, __float_as_uint(bb.z), __float_as_uint(bb.w)); }

#define MMA4(BLK, U) \
        float d00[4] = {0.f,0.f,0.f,0.f}, d01[4] = {0.f,0.f,0.f,0.f}; \
        float d10[4] = {0.f,0.f,0.f,0.f}, d11[4] = {0.f,0.f,0.f,0.f}; \
        { float4 bv = Bp[((BLK)*16 + (U)) * 32]; \
          uint32_t b0 = __float_as_uint(bv.x), b1 = __float_as_uint(bv.y); \
          uint32_t b2w = __float_as_uint(bv.z), b3 = __float_as_uint(bv.w); \
          mma16(d00[0], d00[1], d00[2], d00[3], a0, b0, b1); \
          mma16(d01[0], d01[1], d01[2], d01[3], a0, b2w, b3); \
          mma16(d10[0], d10[1], d10[2], d10[3], a1, b0, b1); \
          mma16(d11[0], d11[1], d11[2], d11[3], a1, b2w, b3); }

#define ACC8S(A, CX, CY, D0, D1) { \
        A[0] += (CX)*D0[0]; A[1] += (CX)*D0[1]; A[4] += (CY)*D0[2]; A[5] += (CY)*D0[3]; \
        A[2] += (CX)*D1[0]; A[3] += (CX)*D1[1]; A[6] += (CY)*D1[2]; A[7] += (CY)*D1[3]; }

        // ---- phase 1: out0 (blocks 0,1) both tiles, then flush ----
        {
            float A0[8] = {}, A1[8] = {};
            { BIAS_A(cs0, 0, b00) BIAS_MMA(A0, b00, 0) }
            { BIAS_A(cs0, 1, b01) BIAS_MMA(A0, b01, 1) }
            { BIAS_A(cs1, 0, b10) BIAS_MMA(A1, b10, 0) }
            { BIAS_A(cs1, 1, b11) BIAS_MMA(A1, b11, 1) }
            #pragma unroll 2
            for (int m = 0; m < 8; m++) {
                float2 c0g0 = h2f2(cs0[0*128 + m*16 + g]), c0h0 = h2f2(cs0[0*128 + m*16 + g+8]);
                float2 c1g0 = h2f2(cs0[1*128 + m*16 + g]), c1h0 = h2f2(cs0[1*128 + m*16 + g+8]);
                float2 c0g1 = h2f2(cs1[0*128 + m*16 + g]), c0h1 = h2f2(cs1[0*128 + m*16 + g+8]);
                float2 c1g1 = h2f2(cs1[1*128 + m*16 + g]), c1h1 = h2f2(cs1[1*128 + m*16 + g+8]);
                #pragma unroll
                for (int q = 0; q < 2; q++) {
                    int u = 2*m + q;
                    { MMA4(0, u)
                      ACC8S(A0, (q?c0g0.y:c0g0.x), (q?c0h0.y:c0h0.x), d00, d01)
                      ACC8S(A1, (q?c0g1.y:c0g1.x), (q?c0h1.y:c0h1.x), d10, d11) }
                    { MMA4(1, u)
                      ACC8S(A0, (q?c1g0.y:c1g0.x), (q?c1h0.y:c1h0.x), d00, d01)
                      ACC8S(A1, (q?c1g1.y:c1g1.x), (q?c1h1.y:c1h1.x), d10, d11) }
                }
            }
            #pragma unroll
            for (int tt = 0; tt < 2; tt++) {
                float* A = tt ? A1 : A0;
                float2 dsg = g_ds[e0 + tt*16 + g];
                float2 dsh = g_ds[e0 + tt*16 + g + 8];
                float* og = out + (size_t)__float_as_int(dsg.x) * 64;
                float* oh = out + (size_t)__float_as_int(dsh.x) * 64;
                RED_V2(og + 2*tig,     dsg.y * A[0], dsg.y * A[1]);
                RED_V2(og + 8 + 2*tig, dsg.y * A[2], dsg.y * A[3]);
                RED_V2(oh + 2*tig,     dsh.y * A[4], dsh.y * A[5]);
                RED_V2(oh + 8 + 2*tig, dsh.y * A[6], dsh.y * A[7]);
            }
        }

        // ---- phase 2: tA (block 2) both tiles ----
        float T0[8] = {}, T1[8] = {};
        { BIAS_A(cs0, 2, b20) BIAS_MMA(T0, b20, 2) }
        { BIAS_A(cs1, 2, b21) BIAS_MMA(T1, b21, 2) }
        #pragma unroll 2
        for (int m = 0; m < 8; m++) {
            float2 cg0 = h2f2(cs0[2*128 + m*16 + g]), ch0 = h2f2(cs0[2*128 + m*16 + g+8]);
            float2 cg1 = h2f2(cs1[2*128 + m*16 + g]), ch1 = h2f2(cs1[2*128 + m*16 + g+8]);
            #pragma unroll
            for (int q = 0; q < 2; q++) {
                int u = 2*m + q;
                MMA4(2, u)
                ACC8S(T0, (q?cg0.y:cg0.x), (q?ch0.y:ch0.x), d00, d01)
                ACC8S(T1, (q?cg1.y:cg1.x), (q?ch1.y:ch1.x), d10, d11)
            }
        }

        // ---- phase 3: blk3 per tile (oA/oB/oC), fused out1 flush ----
        #pragma unroll
        for (int tt = 0; tt < 2; tt++) {
            uint32_t* ct = tt ? cs1 : cs0;
            const uint32_t* at = tt ? a1 : a0;
            float* T = tt ? T1 : T0;
            float P[8] = {}, Q[8] = {}, R[8] = {};
            { BIAS_A(ct, 3, b3) BIAS_MMA(P, b3, 3) }
            { BIAS_A(ct, 4, b4) BIAS_MMA(Q, b4, 3) }
            { BIAS_A(ct, 5, b5) BIAS_MMA(R, b5, 3) }
            #pragma unroll 2
            for (int m = 0; m < 8; m++) {
                float2 pg = h2f2(ct[3*128 + m*16 + g]), ph = h2f2(ct[3*128 + m*16 + g+8]);
                float2 qg = h2f2(ct[4*128 + m*16 + g]), qh = h2f2(ct[4*128 + m*16 + g+8]);
                float2 rg = h2f2(ct[5*128 + m*16 + g]), rh = h2f2(ct[5*128 + m*16 + g+8]);
                #pragma unroll
                for (int q2 = 0; q2 < 2; q2++) {
                    int u = 2*m + q2;
                    float dd0[4] = {0.f,0.f,0.f,0.f}, dd1[4] = {0.f,0.f,0.f,0.f};
                    { float4 bv = Bp[(3*16 + u) * 32];
                      mma16(dd0[0], dd0[1], dd0[2], dd0[3], at,
                            __float_as_uint(bv.x), __float_as_uint(bv.y));
                      mma16(dd1[0], dd1[1], dd1[2], dd1[3], at,
                            __float_as_uint(bv.z), __float_as_uint(bv.w)); }
                    ACC8S(P, (q2?pg.y:pg.x), (q2?ph.y:ph.x), dd0, dd1)
                    ACC8S(Q, (q2?qg.y:qg.x), (q2?qh.y:qh.x), dd0, dd1)
                    ACC8S(R, (q2?rg.y:rg.x), (q2?rh.y:rh.x), dd0, dd1)
                }
            }
            // flush out1 for this tile
            #pragma unroll
            for (int r2 = 0; r2 < 2; r2++) {
                int eg = e0 + tt*16 + g + r2*8;
                float4 sh = edge_sh4[eg];
                float2 ds = g_ds[eg];
                float sca = ds.y;
                float* o = out + (size_t)__float_as_int(ds.x) * 64;
                #pragma unroll
                for (int wh = 0; wh < 2; wh++) {
                    int i0 = r2*4 + wh*2, i1 = i0 + 1;
                    float* ob = o + 16 + 24*wh + 6*tig;
                    float t0 = T[i0], t1 = T[i1];
                    RED_V2(ob,     sca * (sh.y*t0 + P[i0]), sca * (sh.z*t0 + Q[i0]));
                    RED_V2(ob + 2, sca * (sh.w*t0 + R[i0]), sca * (sh.y*t1 + P[i1]));
                    RED_V2(ob + 4, sca * (sh.z*t1 + Q[i1]), sca * (sh.w*t1 + R[i1]));
                }
            }
        }
#undef BIAS_A
#undef BIAS_MMA
#undef MMA4
#undef ACC8S
    }
}

extern "C" void kernel_launch(void* const* d_in, const int* in_sizes, int n_in,
                              void* d_out, int out_size) {
    const float* node_attr  = (const float*)d_in[0];
    const void*  edge_index = d_in[1];
    const float* edge_attr  = (const float*)d_in[2];
    const float* edge_sh    = (const float*)d_in[3];
    const float* w1 = (const float*)d_in[4];
    const float* b1 = (const float*)d_in[5];
    const float* w2 = (const float*)d_in[6];
    const float* b2 = (const float*)d_in[7];
    float* out = (float*)d_out;

    cudaFuncSetAttribute(conv_kernel, cudaFuncAttributeMaxDynamicSharedMemorySize, SM_BYTES);

    int smCount = 148;
    cudaDeviceGetAttribute(&smCount, cudaDevAttrMultiProcessorCount, 0);

    zero_kernel<<<(OUT_ELEMS + 255) / 256, 256>>>((const unsigned*)edge_index, out, w2, b2);
    prep_kernel<<<(N_EDGES + 255) / 256, 256>>>((const int*)edge_index);
    h_kernel<<<(N_EDGES + 255) / 256, 256>>>(edge_attr, w1, b1);
    conv_kernel<<<152, THREADS, SM_BYTES>>>(node_attr, (const float4*)edge_sh, out);
}